// round 12
// baseline (speedup 1.0000x reference)
#include <cuda_runtime.h>
#include <cuda_bf16.h>
#include <math.h>
#include <stdint.h>

// Problem constants
#define B_SZ    512
#define DFEAT   2048
#define DATTR   312
#define DATTR_P 320              // N padded to 4*80
#define NCLS_P  152              // class table stride

// GEMM tiling: D[512,320] = X[512,2048] @ W^T, bf16 hi/lo x4-term split
#define MT_BLK  128              // M per CTA
#define NT_BLK  80               // N per CTA -> 4 n-tiles, grid 128 = one wave
#define BKT     32               // K per smem tile
#define KSPLIT  8
#define KSLICE  (DFEAT / KSPLIT) // 256

// Scratch (__device__ globals: allocation-free, zero-initialized at load)
__device__ __nv_bfloat16 g_WhiT[DATTR_P * DFEAT];   // W^T K-major; rows >=312 stay 0
__device__ __nv_bfloat16 g_WloT[DATTR_P * DFEAT];
__device__ float g_partial[KSPLIT][B_SZ][DATTR_P];
__device__ float g_Sf[B_SZ];
__device__ unsigned int g_done;                     // reset by the tail each call

// ---------------------------------------------------------------------------
// Kernel 0: W [2048,312] -> W^T [320,2048] bf16 hi/lo, vectorized.
// grid (10 n-tiles of 32, 32 k-tiles of 64) = 320 blocks, 256 threads.
// ---------------------------------------------------------------------------
__global__ __launch_bounds__(256) void split_w_kernel(const float* __restrict__ Wm)
{
    __shared__ float t[64][33];
    const int n0 = blockIdx.x * 32, k0 = blockIdx.y * 64;
    const int tid = threadIdx.x;

    {
        const int r = tid >> 2, q = tid & 3;
        #pragma unroll
        for (int h = 0; h < 2; h++) {
            const int qq = q + 4 * h;
            const int n = n0 + qq * 4;
            const float4 v = (n < DATTR)
                ? *(const float4*)(Wm + (size_t)(k0 + r) * DATTR + n)
                : make_float4(0.f, 0.f, 0.f, 0.f);
            t[r][qq * 4 + 0] = v.x;
            t[r][qq * 4 + 1] = v.y;
            t[r][qq * 4 + 2] = v.z;
            t[r][qq * 4 + 3] = v.w;
        }
    }
    __syncthreads();

    {
        const int nl = tid >> 3, kc = tid & 7;
        const int n = n0 + nl;
        if (n < DATTR) {
            __nv_bfloat16 hi[8], lo[8];
            #pragma unroll
            for (int j = 0; j < 8; j++) {
                const float v = t[kc * 8 + j][nl];
                hi[j] = __float2bfloat16_rn(v);
                lo[j] = __float2bfloat16_rn(v - __bfloat162float(hi[j]));
            }
            const size_t off = (size_t)n * DFEAT + k0 + kc * 8;
            *(uint4*)(g_WhiT + off) = *(const uint4*)hi;
            *(uint4*)(g_WloT + off) = *(const uint4*)lo;
        }
    }
}

// ---------------------------------------------------------------------------
// Kernel 1: fused bf16 mma.sync GEMM with inline X hi/lo split.
// grid (4 n-tiles, 4 m-tiles, 8 k-slices) = 128 CTAs (one wave), 256 threads.
// ---------------------------------------------------------------------------
__global__ __launch_bounds__(256) void mma_gemm_kernel(const float* __restrict__ X)
{
    __shared__ __nv_bfloat16 sAhi[MT_BLK][40];
    __shared__ __nv_bfloat16 sAlo[MT_BLK][40];
    __shared__ __nv_bfloat16 sBhi[NT_BLK][40];
    __shared__ __nv_bfloat16 sBlo[NT_BLK][40];

    const int tid   = threadIdx.x;
    const int wid   = tid >> 5;
    const int lane  = tid & 31;
    const int warpM = wid >> 1;          // 0..3
    const int warpN = wid & 1;           // 0..1
    const int nt = blockIdx.x, mt = blockIdx.y, zs = blockIdx.z;

    const int mBase = mt * MT_BLK;
    const int nBase = nt * NT_BLK;
    const int k0    = zs * KSLICE;

    const int lq = lane >> 2;
    const int lr = lane & 3;

    float4 xa[4];
    uint4  wh0, wl0, wh1, wl1;
    const int arow  = tid >> 3, ac = tid & 7;
    const int wrow0 = tid >> 2, wc0 = tid & 3;
    const int wrow1 = 64 + (tid >> 2);
    const bool bsec = (tid < 64);

    float acc[2][5][4] = {};

    {
        const int k = k0;
        #pragma unroll
        for (int it = 0; it < 4; it++)
            xa[it] = *(const float4*)(X + (size_t)(mBase + arow + 32 * it) * DFEAT + k + ac * 4);
        wh0 = *(const uint4*)(g_WhiT + (size_t)(nBase + wrow0) * DFEAT + k + wc0 * 8);
        wl0 = *(const uint4*)(g_WloT + (size_t)(nBase + wrow0) * DFEAT + k + wc0 * 8);
        if (bsec) {
            wh1 = *(const uint4*)(g_WhiT + (size_t)(nBase + wrow1) * DFEAT + k + wc0 * 8);
            wl1 = *(const uint4*)(g_WloT + (size_t)(nBase + wrow1) * DFEAT + k + wc0 * 8);
        }
    }

    for (int kt = 0; kt < KSLICE; kt += BKT) {
        #pragma unroll
        for (int it = 0; it < 4; it++) {
            const float4 v = xa[it];
            const int row = arow + 32 * it;
            const __nv_bfloat16 h0 = __float2bfloat16_rn(v.x), h1 = __float2bfloat16_rn(v.y);
            const __nv_bfloat16 h2 = __float2bfloat16_rn(v.z), h3 = __float2bfloat16_rn(v.w);
            *(__nv_bfloat162*)&sAhi[row][ac * 4]     = __nv_bfloat162(h0, h1);
            *(__nv_bfloat162*)&sAhi[row][ac * 4 + 2] = __nv_bfloat162(h2, h3);
            *(__nv_bfloat162*)&sAlo[row][ac * 4] = __nv_bfloat162(
                __float2bfloat16_rn(v.x - __bfloat162float(h0)),
                __float2bfloat16_rn(v.y - __bfloat162float(h1)));
            *(__nv_bfloat162*)&sAlo[row][ac * 4 + 2] = __nv_bfloat162(
                __float2bfloat16_rn(v.z - __bfloat162float(h2)),
                __float2bfloat16_rn(v.w - __bfloat162float(h3)));
        }
        *(uint4*)&sBhi[wrow0][wc0 * 8] = wh0;
        *(uint4*)&sBlo[wrow0][wc0 * 8] = wl0;
        if (bsec) {
            *(uint4*)&sBhi[wrow1][wc0 * 8] = wh1;
            *(uint4*)&sBlo[wrow1][wc0 * 8] = wl1;
        }
        __syncthreads();

        if (kt + BKT < KSLICE) {
            const int k = k0 + kt + BKT;
            #pragma unroll
            for (int it = 0; it < 4; it++)
                xa[it] = *(const float4*)(X + (size_t)(mBase + arow + 32 * it) * DFEAT + k + ac * 4);
            wh0 = *(const uint4*)(g_WhiT + (size_t)(nBase + wrow0) * DFEAT + k + wc0 * 8);
            wl0 = *(const uint4*)(g_WloT + (size_t)(nBase + wrow0) * DFEAT + k + wc0 * 8);
            if (bsec) {
                wh1 = *(const uint4*)(g_WhiT + (size_t)(nBase + wrow1) * DFEAT + k + wc0 * 8);
                wl1 = *(const uint4*)(g_WloT + (size_t)(nBase + wrow1) * DFEAT + k + wc0 * 8);
            }
        }

        #pragma unroll
        for (int kk = 0; kk < BKT; kk += 16) {
            uint32_t ahi[2][4], alo[2][4];
            #pragma unroll
            for (int am = 0; am < 2; am++) {
                const int r = warpM * 32 + am * 16 + lq;
                ahi[am][0] = *(const uint32_t*)&sAhi[r    ][kk + lr * 2    ];
                ahi[am][1] = *(const uint32_t*)&sAhi[r + 8][kk + lr * 2    ];
                ahi[am][2] = *(const uint32_t*)&sAhi[r    ][kk + lr * 2 + 8];
                ahi[am][3] = *(const uint32_t*)&sAhi[r + 8][kk + lr * 2 + 8];
                alo[am][0] = *(const uint32_t*)&sAlo[r    ][kk + lr * 2    ];
                alo[am][1] = *(const uint32_t*)&sAlo[r + 8][kk + lr * 2    ];
                alo[am][2] = *(const uint32_t*)&sAlo[r    ][kk + lr * 2 + 8];
                alo[am][3] = *(const uint32_t*)&sAlo[r + 8][kk + lr * 2 + 8];
            }
            uint32_t bhi[5][2], blo[5][2];
            #pragma unroll
            for (int bn = 0; bn < 5; bn++) {
                const int n = warpN * 40 + bn * 8 + lq;
                bhi[bn][0] = *(const uint32_t*)&sBhi[n][kk + lr * 2    ];
                bhi[bn][1] = *(const uint32_t*)&sBhi[n][kk + lr * 2 + 8];
                blo[bn][0] = *(const uint32_t*)&sBlo[n][kk + lr * 2    ];
                blo[bn][1] = *(const uint32_t*)&sBlo[n][kk + lr * 2 + 8];
            }
            #pragma unroll
            for (int am = 0; am < 2; am++) {
                #pragma unroll
                for (int bn = 0; bn < 5; bn++) {
                    float* c = acc[am][bn];
                    #define MMA(AV, BV)                                               \
                        asm volatile(                                                  \
                            "mma.sync.aligned.m16n8k16.row.col.f32.bf16.bf16.f32 "    \
                            "{%0,%1,%2,%3}, {%4,%5,%6,%7}, {%8,%9}, {%0,%1,%2,%3};"   \
                            : "+f"(c[0]), "+f"(c[1]), "+f"(c[2]), "+f"(c[3])           \
                            : "r"(AV[0]), "r"(AV[1]), "r"(AV[2]), "r"(AV[3]),          \
                              "r"(BV[0]), "r"(BV[1]))
                    MMA(ahi[am], bhi[bn]);
                    MMA(ahi[am], blo[bn]);
                    MMA(alo[am], bhi[bn]);
                    MMA(alo[am], blo[bn]);
                    #undef MMA
                }
            }
        }
        __syncthreads();
    }

    #pragma unroll
    for (int am = 0; am < 2; am++) {
        const int row0 = mBase + warpM * 32 + am * 16 + lq;
        #pragma unroll
        for (int bn = 0; bn < 5; bn++) {
            const int col = nBase + warpN * 40 + bn * 8 + lr * 2;
            *(float2*)&g_partial[zs][row0    ][col] = make_float2(acc[am][bn][0], acc[am][bn][1]);
            *(float2*)&g_partial[zs][row0 + 8][col] = make_float2(acc[am][bn][2], acc[am][bn][3]);
        }
    }
}

// ---------------------------------------------------------------------------
// Kernel 2 (fused): per-row S[i], then the LAST block computes the pair loss
// with the O(B) class-rank method. grid 512, block 256.
//   loss_sum = sum_t coef_t * (S_t - S_0),  coef_t = 2*rank_t + 1 - cnt_all_t
//   pairs    = sum_t rank_t
// rank via per-virtual-warp class table + __match_any_sync; double dot kills
// fp32 cancellation (sum(coef)=0 per class makes the S_0 shift exact).
// ---------------------------------------------------------------------------
__global__ __launch_bounds__(256) void rowstats_pair_kernel(
    const float* __restrict__ bvec, const int* __restrict__ labw,
    float* __restrict__ out)
{
    const int i   = blockIdx.x;
    const int tid = threadIdx.x;

    __shared__ float vhalf[2][DATTR_P];
    __shared__ float vals[DATTR_P];
    __shared__ float sred[8], sse[8], srs[8];

    if (tid < 160) {
        const int half = (tid < 80) ? 0 : 1;
        const int c4   = (tid < 80) ? tid : (tid - 80);
        float4 a = make_float4(0.f, 0.f, 0.f, 0.f);
        #pragma unroll
        for (int s = 0; s < 4; s++) {
            const float4 p = *(const float4*)&g_partial[half * 4 + s][i][c4 * 4];
            a.x += p.x; a.y += p.y; a.z += p.z; a.w += p.w;
        }
        *(float4*)&vhalf[half][c4 * 4] = a;
    }
    __syncthreads();
    if (tid < 80) {
        float4 a = *(const float4*)&vhalf[0][tid * 4];
        const float4 c = *(const float4*)&vhalf[1][tid * 4];
        const float4 bb = (tid < 78) ? *(const float4*)(bvec + tid * 4)
                                     : make_float4(0.f, 0.f, 0.f, 0.f);
        a.x += c.x + bb.x; a.y += c.y + bb.y;
        a.z += c.z + bb.z; a.w += c.w + bb.w;
        *(float4*)&vals[tid * 4] = a;
    }
    __syncthreads();

    float m = -1e30f;
    for (int c = tid; c < DATTR; c += 256) m = fmaxf(m, vals[c]);
    #pragma unroll
    for (int o = 16; o; o >>= 1) m = fmaxf(m, __shfl_xor_sync(0xffffffffu, m, o));
    if ((tid & 31) == 0) sred[tid >> 5] = m;
    __syncthreads();
    m = sred[0];
    #pragma unroll
    for (int w = 1; w < 8; w++) m = fmaxf(m, sred[w]);

    float se = 0.f, rs = 0.f;
    for (int c = tid; c < DATTR; c += 256) {
        const float v = vals[c];
        se += expf(v - m);
        rs += v;
    }
    #pragma unroll
    for (int o = 16; o; o >>= 1) {
        se += __shfl_xor_sync(0xffffffffu, se, o);
        rs += __shfl_xor_sync(0xffffffffu, rs, o);
    }
    if ((tid & 31) == 0) { sse[tid >> 5] = se; srs[tid >> 5] = rs; }
    __syncthreads();

    if (tid == 0) {
        float seT = 0.f, rsT = 0.f;
        #pragma unroll
        for (int w = 0; w < 8; w++) { seT += sse[w]; rsT += srs[w]; }
        g_Sf[i] = rsT - (float)DATTR * (m + logf(seT));
    }

    // ---- last-block pair-loss tail ----
    __shared__ int s_last;
    __threadfence();
    if (tid == 0) {
        const unsigned int old = atomicAdd(&g_done, 1u);
        s_last = (old == (unsigned int)(gridDim.x - 1));
    }
    __syncthreads();
    if (!s_last) return;

    __shared__ int           table[16][NCLS_P];
    __shared__ int           s_not64;
    __shared__ double        swsum[8];
    __shared__ unsigned int  swcnt[8];

    if (tid == 0) s_not64 = 0;
    for (int idx = tid; idx < 16 * NCLS_P; idx += 256)
        ((int*)table)[idx] = 0;
    __syncthreads();

    // label dtype sniff: int64 buffers have zero odd words (labels < 150)
    if (labw[2 * tid + 1] != 0) atomicOr(&s_not64, 1);
    __syncthreads();
    const bool is64 = (s_not64 == 0);

    // each thread owns elements e0 = tid, e1 = tid + 256
    const int e0 = tid, e1 = tid + 256;
    const int l0 = is64 ? labw[2 * e0] : labw[e0];
    const int l1 = is64 ? labw[2 * e1] : labw[e1];
    atomicAdd(&table[e0 >> 5][l0], 1);
    atomicAdd(&table[e1 >> 5][l1], 1);
    __syncthreads();

    const int      lane   = tid & 31;
    const unsigned lt     = (1u << lane) - 1u;
    const unsigned mm0    = __match_any_sync(0xffffffffu, l0);
    const unsigned mm1    = __match_any_sync(0xffffffffu, l1);
    const int      vw0    = e0 >> 5;          // 0..7
    const int      vw1    = e1 >> 5;          // 8..15

    int rank0 = __popc(mm0 & lt), rank1 = __popc(mm1 & lt);
    int all0 = 0, all1 = 0;
    #pragma unroll
    for (int w = 0; w < 16; w++) {
        const int c0 = table[w][l0];
        const int c1 = table[w][l1];
        all0 += c0;  all1 += c1;
        if (w < vw0) rank0 += c0;
        if (w < vw1) rank1 += c1;
    }

    const float ref = __ldcg(&g_Sf[0]);
    double local =
        (double)(2 * rank0 + 1 - all0) * (double)(__ldcg(&g_Sf[e0]) - ref) +
        (double)(2 * rank1 + 1 - all1) * (double)(__ldcg(&g_Sf[e1]) - ref);
    unsigned int cnt = (unsigned int)(rank0 + rank1);

    #pragma unroll
    for (int o = 16; o; o >>= 1) {
        local += __shfl_xor_sync(0xffffffffu, local, o);
        cnt   += __shfl_xor_sync(0xffffffffu, cnt, o);
    }
    if (lane == 0) { swsum[tid >> 5] = local; swcnt[tid >> 5] = cnt; }
    __syncthreads();

    if (tid == 0) {
        double s = 0.0; unsigned int c = 0;
        #pragma unroll
        for (int w = 0; w < 8; w++) { s += swsum[w]; c += swcnt[w]; }
        out[0] = (float)((c > 0) ? (s / (double)c) : s);
        g_done = 0;   // reset for next graph replay (deterministic)
    }
}

// ---------------------------------------------------------------------------
extern "C" void kernel_launch(void* const* d_in, const int* in_sizes, int n_in,
                              void* d_out, int out_size)
{
    const float* x   = (const float*)d_in[0];      // [512, 2048]
    const float* Wm  = (const float*)d_in[1];      // [2048, 312]
    const float* b   = (const float*)d_in[2];      // [312]
    // d_in[3] = seen_att : unused (cancels exactly for same-label pairs)
    const int*   lab = (const int*)d_in[4];        // [512] labels

    split_w_kernel<<<dim3(10, 32), 256>>>(Wm);
    mma_gemm_kernel<<<dim3(DATTR_P / NT_BLK, B_SZ / MT_BLK, KSPLIT), 256>>>(x);
    rowstats_pair_kernel<<<B_SZ, 256>>>(b, lab, (float*)d_out);
}